// round 3
// baseline (speedup 1.0000x reference)
#include <cuda_runtime.h>
#include <math.h>

// Problem constants
#define B_  32
#define C_  1024
#define M_  1024
#define D_  512
#define R_  64
#define NCC 16   // c-chunks for KV partial sums

// Scratch (device globals: allocation-free per harness rules)
__device__ float g_Tsum[B_ * C_];          // (b,c)  = sum_m T[b,c,m]
__device__ float g_rsum[R_];               // (r)    = sum_m R[r,m]
__device__ float g_partK[NCC * B_ * D_];   // partial Ksum per c-chunk
__device__ float g_partV[NCC * B_ * D_];
__device__ float g_Ksum[B_ * D_];          // (b,d)  = sum_c Tsum*Wk
__device__ float g_Vsum[B_ * D_];
__device__ float g_u[B_ * C_];             // (b,c)  = scale * sum_d Wq[c,d]*Ksum[b,d]
__device__ float g_y[B_ * C_];             // (b,c)  = sum_d Vsum[b,d]*Wout[d,c]
__device__ float g_w[B_ * M_];             // (b,i)  = softmax-weighted rsum

// ---------------------------------------------------------------------------
// K1: row sums of T (B*C rows) and R_full (R rows). One warp per row.
// ---------------------------------------------------------------------------
__global__ void __launch_bounds__(256)
k_rowsum(const float* __restrict__ T, const float* __restrict__ Rf)
{
    const int gw   = (blockIdx.x * 256 + threadIdx.x) >> 5;
    const int lane = threadIdx.x & 31;
    const float* src;
    float* dst;
    if (gw < B_ * C_)            { src = T  + (long)gw * M_;              dst = g_Tsum + gw; }
    else if (gw < B_ * C_ + R_)  { src = Rf + (long)(gw - B_ * C_) * M_;  dst = g_rsum + (gw - B_ * C_); }
    else return;

    double acc = 0.0;
    #pragma unroll
    for (int j = 0; j < M_ / 128; ++j) {
        float4 v = *(const float4*)&src[j * 128 + lane * 4];
        acc += ((double)v.x + (double)v.y) + ((double)v.z + (double)v.w);
    }
    #pragma unroll
    for (int off = 16; off; off >>= 1)
        acc += __shfl_xor_sync(0xffffffffu, acc, off);
    if (lane == 0) *dst = (float)acc;
}

// ---------------------------------------------------------------------------
// K2: partial Ksum/Vsum over a 64-wide c-chunk.
// grid (NCC, B/4), 512 threads (one per d). Coalesced Wk/Wv reads.
// ---------------------------------------------------------------------------
__global__ void __launch_bounds__(512)
k_kv_partial(const float* __restrict__ Wk, const float* __restrict__ Wv)
{
    __shared__ float ts[4][64];
    const int d  = threadIdx.x;
    const int c0 = blockIdx.x * 64;
    const int b0 = blockIdx.y * 4;

    if (threadIdx.x < 256) {
        const int j = threadIdx.x >> 6, cc = threadIdx.x & 63;
        ts[j][cc] = g_Tsum[(b0 + j) * C_ + c0 + cc];
    }
    __syncthreads();

    float aK[4] = {}, aV[4] = {};
    #pragma unroll 2
    for (int cc = 0; cc < 64; ++cc) {
        const float wk = Wk[(long)(c0 + cc) * D_ + d];
        const float wv = Wv[(long)(c0 + cc) * D_ + d];
        #pragma unroll
        for (int j = 0; j < 4; ++j) {
            aK[j] = fmaf(ts[j][cc], wk, aK[j]);
            aV[j] = fmaf(ts[j][cc], wv, aV[j]);
        }
    }
    #pragma unroll
    for (int j = 0; j < 4; ++j) {
        g_partK[((long)blockIdx.x * B_ + b0 + j) * D_ + d] = aK[j];
        g_partV[((long)blockIdx.x * B_ + b0 + j) * D_ + d] = aV[j];
    }
}

// K2b: combine partials in double. grid (B), 512 threads.
__global__ void __launch_bounds__(512)
k_kv_combine()
{
    const int b = blockIdx.x, d = threadIdx.x;
    double sK = 0, sV = 0;
    #pragma unroll
    for (int p = 0; p < NCC; ++p) {
        sK += g_partK[((long)p * B_ + b) * D_ + d];
        sV += g_partV[((long)p * B_ + b) * D_ + d];
    }
    g_Ksum[b * D_ + d] = (float)sK;
    g_Vsum[b * D_ + d] = (float)sV;
}

// ---------------------------------------------------------------------------
// K3: u[b,c] = scale * sum_d Wq[c,d]*Ksum[b,d]; y[b,c] = sum_d Wout[d,c]*Vsum[b,d]
// grid (C/16), 256 threads. 64-term float chunks promoted to double.
// ---------------------------------------------------------------------------
__global__ void __launch_bounds__(256)
k_uy(const float* __restrict__ Wq, const float* __restrict__ Wout, float scale)
{
    __shared__ float wq_s[16][65];
    __shared__ float wo_s[64][17];
    __shared__ float ks_s[32][65];
    __shared__ float vs_s[32][65];
    const int c0 = blockIdx.x * 16;
    const int t  = threadIdx.x;
    const int c  = t & 15;
    const int bp = t >> 4;                 // 0..15, b = bp*2 + j

    double uU[2] = {}, uY[2] = {};
    for (int dc = 0; dc < D_ / 64; ++dc) {
        const int d0 = dc * 64;
        __syncthreads();
        for (int idx = t; idx < 16 * 64; idx += 256) {
            const int r = idx >> 6, col = idx & 63;
            wq_s[r][col] = Wq[(long)(c0 + r) * D_ + d0 + col];
        }
        for (int idx = t; idx < 64 * 16; idx += 256) {
            const int r = idx >> 4, col = idx & 15;
            wo_s[r][col] = Wout[(long)(d0 + r) * C_ + c0 + col];
        }
        for (int idx = t; idx < 32 * 64; idx += 256) {
            const int b = idx >> 6, dd = idx & 63;
            ks_s[b][dd] = g_Ksum[b * D_ + d0 + dd];
            vs_s[b][dd] = g_Vsum[b * D_ + d0 + dd];
        }
        __syncthreads();

        float fU[2] = {}, fY[2] = {};
        #pragma unroll 4
        for (int dd = 0; dd < 64; ++dd) {
            const float wq = wq_s[c][dd];
            const float wo = wo_s[dd][c];
            #pragma unroll
            for (int j = 0; j < 2; ++j) {
                fU[j] = fmaf(wq, ks_s[bp * 2 + j][dd], fU[j]);
                fY[j] = fmaf(wo, vs_s[bp * 2 + j][dd], fY[j]);
            }
        }
        #pragma unroll
        for (int j = 0; j < 2; ++j) { uU[j] += (double)fU[j]; uY[j] += (double)fY[j]; }
    }
    #pragma unroll
    for (int j = 0; j < 2; ++j) {
        const int b = bp * 2 + j;
        g_u[b * C_ + c0 + c] = (float)(uU[j] * (double)scale);
        g_y[b * C_ + c0 + c] = (float)uY[j];
    }
}

// ---------------------------------------------------------------------------
// K4: x[b,i] = sum_c T[b,c,i]*u[b,c]  (second sweep of T), then fused
//     softmax over r of x*rsum[r] -> w[b,i] = sum_r A*rsum[r].
// grid (M/128, B), 512 threads: i = t&127, c-group = t>>7 (4 x 256 c).
// ---------------------------------------------------------------------------
__global__ void __launch_bounds__(512)
k_scores(const float* __restrict__ T)
{
    __shared__ float  u_s[C_];
    __shared__ float  rs_s[R_];
    __shared__ double red[512];
    const int t  = threadIdx.x;
    const int b  = blockIdx.y;
    const int i0 = blockIdx.x * 128;
    const int i  = t & 127;
    const int cg = t >> 7;

    u_s[t]       = g_u[b * C_ + t];
    u_s[t + 512] = g_u[b * C_ + t + 512];
    if (t < R_) rs_s[t] = g_rsum[t];
    __syncthreads();

    const float* Tp = T + ((long)b * C_ + cg * 256) * M_ + i0 + i;
    const float* up = u_s + cg * 256;
    double a0 = 0, a1 = 0, a2 = 0, a3 = 0;
    #pragma unroll 4
    for (int c = 0; c < 256; c += 4) {
        a0 += (double)Tp[(long)(c + 0) * M_] * up[c + 0];
        a1 += (double)Tp[(long)(c + 1) * M_] * up[c + 1];
        a2 += (double)Tp[(long)(c + 2) * M_] * up[c + 2];
        a3 += (double)Tp[(long)(c + 3) * M_] * up[c + 3];
    }
    red[t] = (a0 + a1) + (a2 + a3);
    __syncthreads();

    if (t < 128) {
        const float x = (float)(red[t] + red[t + 128] + red[t + 256] + red[t + 384]);
        float mx = -1e30f;
        #pragma unroll
        for (int r = 0; r < R_; ++r) mx = fmaxf(mx, x * rs_s[r]);
        float num = 0.f, den = 0.f;
        #pragma unroll
        for (int r = 0; r < R_; ++r) {
            const float e = expf(x * rs_s[r] - mx);
            den += e;
            num = fmaf(rs_s[r], e, num);
        }
        g_w[b * M_ + i0 + t] = num / den;
    }
}

// ---------------------------------------------------------------------------
// K6: out[b,c,i] = w[b,i] * y[b,c]. grid (B*C/4), 256 threads, float4 stores.
// ---------------------------------------------------------------------------
__global__ void __launch_bounds__(256)
k_outer(float* __restrict__ Out)
{
    const int t  = threadIdx.x;
    const int b  = blockIdx.x >> 8;
    const int c0 = (blockIdx.x & 255) * 4;
    const float4 w4 = *(const float4*)&g_w[b * M_ + t * 4];
    #pragma unroll
    for (int j = 0; j < 4; ++j) {
        const float yv = g_y[b * C_ + c0 + j];
        float4 o = make_float4(w4.x * yv, w4.y * yv, w4.z * yv, w4.w * yv);
        *(float4*)&Out[((long)b * C_ + c0 + j) * M_ + t * 4] = o;
    }
}

// ---------------------------------------------------------------------------
extern "C" void kernel_launch(void* const* d_in, const int* in_sizes, int n_in,
                              void* d_out, int out_size)
{
    (void)in_sizes; (void)n_in; (void)out_size;
    const float* T     = (const float*)d_in[0];   // (B, C, M)
    const float* Wq    = (const float*)d_in[1];   // (C, D)
    const float* Wk    = (const float*)d_in[2];   // (C, D)
    const float* Wv    = (const float*)d_in[3];   // (C, DV)
    const float* Wout  = (const float*)d_in[4];   // (DV, C)
    const float* Rfull = (const float*)d_in[5];   // (R, M)
    float* Out = (float*)d_out;                   // (B, C, M)

    const float scale = 1.0f / sqrtf((float)D_);

    // 1) row sums of T and R_full
    {
        const int nwarps = B_ * C_ + R_;
        k_rowsum<<<(nwarps + 7) / 8, 256>>>(T, Rfull);
    }
    // 2) Ksum/Vsum partials + combine
    k_kv_partial<<<dim3(NCC, B_ / 4), 512>>>(Wk, Wv);
    k_kv_combine<<<B_, 512>>>();
    // 3) u and y
    k_uy<<<C_ / 16, 256>>>(Wq, Wout, scale);
    // 4) x + softmax -> w (second sweep of T)
    k_scores<<<dim3(M_ / 128, B_), 512>>>(T);
    // 5) rank-1 outer product output
    k_outer<<<B_ * 256, 256>>>(Out);
}

// round 5
// speedup vs baseline: 2.8694x; 2.8694x over previous
#include <cuda_runtime.h>
#include <math.h>

// Problem constants
#define B_  32
#define C_  1024
#define M_  1024
#define D_  512
#define R_  64
#define NCC 16   // c-chunks for KV partial sums

// Scratch (device globals: allocation-free per harness rules)
__device__ float g_Tsum[B_ * C_];          // (b,c)  = sum_m T[b,c,m]
__device__ float g_rsum[R_];               // (r)    = sum_m R[r,m]
__device__ float g_partK[NCC * B_ * D_];   // partial Ksum per c-chunk
__device__ float g_partV[NCC * B_ * D_];
__device__ float g_Ksum[B_ * D_];
__device__ float g_Vsum[B_ * D_];
__device__ float g_u[B_ * C_];             // scale * Wq . Ksum
__device__ float g_y[B_ * C_];             // Vsum . Wout[:,c]
__device__ float g_w[B_ * M_];             // softmax-weighted rsum

// ---------------------------------------------------------------------------
// K1: row sums of T (B*C rows) and R_full (R rows). One warp per row, float4,
// 4 independent accumulators (MLP 8 via unroll).
// ---------------------------------------------------------------------------
__global__ void __launch_bounds__(256)
k_rowsum(const float* __restrict__ T, const float* __restrict__ Rf)
{
    const int gw   = (blockIdx.x * 256 + threadIdx.x) >> 5;
    const int lane = threadIdx.x & 31;
    const float* src;
    float* dst;
    if (gw < B_ * C_)            { src = T  + (long)gw * M_;              dst = g_Tsum + gw; }
    else if (gw < B_ * C_ + R_)  { src = Rf + (long)(gw - B_ * C_) * M_;  dst = g_rsum + (gw - B_ * C_); }
    else return;

    float s0 = 0.f, s1 = 0.f, s2 = 0.f, s3 = 0.f;
    #pragma unroll
    for (int j = 0; j < M_ / 256; ++j) {          // 4 iterations, 2 loads each
        float4 a = *(const float4*)&src[j * 256 + lane * 4];
        float4 b = *(const float4*)&src[j * 256 + 128 + lane * 4];
        s0 += a.x + a.y; s1 += a.z + a.w;
        s2 += b.x + b.y; s3 += b.z + b.w;
    }
    float acc = (s0 + s1) + (s2 + s3);
    #pragma unroll
    for (int off = 16; off; off >>= 1)
        acc += __shfl_xor_sync(0xffffffffu, acc, off);
    if (lane == 0) *dst = acc;
}

// ---------------------------------------------------------------------------
// K2: partial Ksum/Vsum over a 64-wide c-chunk. grid (NCC, B/4), 512 threads.
// ---------------------------------------------------------------------------
__global__ void __launch_bounds__(512)
k_kv_partial(const float* __restrict__ Wk, const float* __restrict__ Wv)
{
    __shared__ float ts[4][64];
    const int d  = threadIdx.x;
    const int c0 = blockIdx.x * 64;
    const int b0 = blockIdx.y * 4;

    if (threadIdx.x < 256) {
        const int j = threadIdx.x >> 6, cc = threadIdx.x & 63;
        ts[j][cc] = g_Tsum[(b0 + j) * C_ + c0 + cc];
    }
    __syncthreads();

    float aK[4] = {}, aV[4] = {};
    #pragma unroll 4
    for (int cc = 0; cc < 64; ++cc) {
        const float wk = Wk[(long)(c0 + cc) * D_ + d];
        const float wv = Wv[(long)(c0 + cc) * D_ + d];
        #pragma unroll
        for (int j = 0; j < 4; ++j) {
            aK[j] = fmaf(ts[j][cc], wk, aK[j]);
            aV[j] = fmaf(ts[j][cc], wv, aV[j]);
        }
    }
    #pragma unroll
    for (int j = 0; j < 4; ++j) {
        g_partK[((long)blockIdx.x * B_ + b0 + j) * D_ + d] = aK[j];
        g_partV[((long)blockIdx.x * B_ + b0 + j) * D_ + d] = aV[j];
    }
}

// K2b: combine partials. grid (B), 512 threads.
__global__ void __launch_bounds__(512)
k_kv_combine()
{
    const int b = blockIdx.x, d = threadIdx.x;
    float sK = 0.f, sV = 0.f;
    #pragma unroll
    for (int p = 0; p < NCC; ++p) {
        sK += g_partK[((long)p * B_ + b) * D_ + d];
        sV += g_partV[((long)p * B_ + b) * D_ + d];
    }
    g_Ksum[b * D_ + d] = sK;
    g_Vsum[b * D_ + d] = sV;
}

// ---------------------------------------------------------------------------
// K3a: u[b,c] = scale * sum_d Wq[c,d]*Ksum[b,d].
// One warp per (b,c); lanes stride d with float4 (Wq rows contiguous,
// Ksum rows broadcast-cached). grid = B*C/8 blocks of 256.
// ---------------------------------------------------------------------------
__global__ void __launch_bounds__(256)
k_u(const float* __restrict__ Wq, float scale)
{
    const int gw   = (blockIdx.x * 256 + threadIdx.x) >> 5;  // (b,c) pair
    const int lane = threadIdx.x & 31;
    const int b = gw >> 10;            // gw / C_
    const int c = gw & 1023;           // gw % C_

    const float* wq = Wq     + (long)c * D_;
    const float* ks = g_Ksum + (long)b * D_;
    float acc = 0.f;
    #pragma unroll
    for (int j = 0; j < D_ / 128; ++j) {        // 4 iterations
        float4 a = *(const float4*)&wq[j * 128 + lane * 4];
        float4 k = *(const float4*)&ks[j * 128 + lane * 4];
        acc += a.x * k.x + a.y * k.y + a.z * k.z + a.w * k.w;
    }
    #pragma unroll
    for (int off = 16; off; off >>= 1)
        acc += __shfl_xor_sync(0xffffffffu, acc, off);
    if (lane == 0) g_u[b * C_ + c] = acc * scale;
}

// ---------------------------------------------------------------------------
// K3b: y[b,c] = sum_d Vsum[b,d]*Wout[d,c].
// grid (C/256, B), 256 threads: thread = c (Wout rows coalesced), Vsum in smem.
// ---------------------------------------------------------------------------
__global__ void __launch_bounds__(256)
k_y(const float* __restrict__ Wout)
{
    __shared__ float vs[D_];
    const int b  = blockIdx.y;
    const int c  = blockIdx.x * 256 + threadIdx.x;
    vs[threadIdx.x]       = g_Vsum[b * D_ + threadIdx.x];
    vs[threadIdx.x + 256] = g_Vsum[b * D_ + threadIdx.x + 256];
    __syncthreads();

    float a0 = 0.f, a1 = 0.f, a2 = 0.f, a3 = 0.f;
    #pragma unroll 8
    for (int d = 0; d < D_; d += 4) {
        a0 = fmaf(vs[d + 0], Wout[(long)(d + 0) * C_ + c], a0);
        a1 = fmaf(vs[d + 1], Wout[(long)(d + 1) * C_ + c], a1);
        a2 = fmaf(vs[d + 2], Wout[(long)(d + 2) * C_ + c], a2);
        a3 = fmaf(vs[d + 3], Wout[(long)(d + 3) * C_ + c], a3);
    }
    g_y[b * C_ + c] = (a0 + a1) + (a2 + a3);
}

// ---------------------------------------------------------------------------
// K4: x[b,i] = sum_c T[b,c,i]*u[b,c], then softmax over r of x*rsum[r]
//     -> w[b,i] = sum_r A*rsum[r].
// grid (M/64, B), 256 threads: i = t&63 (64-wide tile), cg = t>>6 (4 x 256 c).
// ---------------------------------------------------------------------------
__global__ void __launch_bounds__(256)
k_scores(const float* __restrict__ T)
{
    __shared__ float u_s[C_];
    __shared__ float rs_s[R_];
    __shared__ float red[256];
    const int t  = threadIdx.x;
    const int b  = blockIdx.y;
    const int i0 = blockIdx.x * 64;
    const int i  = t & 63;
    const int cg = t >> 6;

    #pragma unroll
    for (int j = 0; j < 4; ++j) u_s[t + j * 256] = g_u[b * C_ + t + j * 256];
    if (t < R_) rs_s[t] = g_rsum[t];
    __syncthreads();

    const float* Tp = T + ((long)b * C_ + cg * 256) * M_ + i0 + i;
    const float* up = u_s + cg * 256;
    float a0 = 0.f, a1 = 0.f, a2 = 0.f, a3 = 0.f;
    #pragma unroll 8
    for (int c = 0; c < 256; c += 4) {
        a0 = fmaf(Tp[(long)(c + 0) * M_], up[c + 0], a0);
        a1 = fmaf(Tp[(long)(c + 1) * M_], up[c + 1], a1);
        a2 = fmaf(Tp[(long)(c + 2) * M_], up[c + 2], a2);
        a3 = fmaf(Tp[(long)(c + 3) * M_], up[c + 3], a3);
    }
    red[t] = (a0 + a1) + (a2 + a3);
    __syncthreads();

    if (t < 64) {
        const float x = red[t] + red[t + 64] + red[t + 128] + red[t + 192];
        float mx = -1e30f;
        #pragma unroll
        for (int r = 0; r < R_; ++r) mx = fmaxf(mx, x * rs_s[r]);
        float num = 0.f, den = 0.f;
        #pragma unroll
        for (int r = 0; r < R_; ++r) {
            const float e = __expf(x * rs_s[r] - mx);
            den += e;
            num = fmaf(rs_s[r], e, num);
        }
        g_w[b * M_ + i0 + t] = num / den;
    }
}

// ---------------------------------------------------------------------------
// K5: out[b,c,i] = w[b,i] * y[b,c]. grid (B*C/4), 256 threads, float4 stores.
// ---------------------------------------------------------------------------
__global__ void __launch_bounds__(256)
k_outer(float* __restrict__ Out)
{
    const int t  = threadIdx.x;
    const int b  = blockIdx.x >> 8;
    const int c0 = (blockIdx.x & 255) * 4;
    const float4 w4 = *(const float4*)&g_w[b * M_ + t * 4];
    #pragma unroll
    for (int j = 0; j < 4; ++j) {
        const float yv = g_y[b * C_ + c0 + j];
        float4 o = make_float4(w4.x * yv, w4.y * yv, w4.z * yv, w4.w * yv);
        *(float4*)&Out[((long)b * C_ + c0 + j) * M_ + t * 4] = o;
    }
}

// ---------------------------------------------------------------------------
extern "C" void kernel_launch(void* const* d_in, const int* in_sizes, int n_in,
                              void* d_out, int out_size)
{
    (void)in_sizes; (void)n_in; (void)out_size;
    const float* T     = (const float*)d_in[0];   // (B, C, M)
    const float* Wq    = (const float*)d_in[1];   // (C, D)
    const float* Wk    = (const float*)d_in[2];   // (C, D)
    const float* Wv    = (const float*)d_in[3];   // (C, DV)
    const float* Wout  = (const float*)d_in[4];   // (DV, C)
    const float* Rfull = (const float*)d_in[5];   // (R, M)
    float* Out = (float*)d_out;                   // (B, C, M)

    const float scale = 1.0f / sqrtf((float)D_);

    // 1) row sums of T and R_full
    k_rowsum<<<(B_ * C_ + R_ + 7) / 8, 256>>>(T, Rfull);
    // 2) Ksum/Vsum
    k_kv_partial<<<dim3(NCC, B_ / 4), 512>>>(Wk, Wv);
    k_kv_combine<<<B_, 512>>>();
    // 3) u and y
    k_u<<<B_ * C_ / 8, 256>>>(Wq, scale);
    k_y<<<dim3(C_ / 256, B_), 256>>>(Wout);
    // 4) x + softmax -> w (second sweep of T)
    k_scores<<<dim3(M_ / 64, B_), 256>>>(T);
    // 5) rank-1 outer product output
    k_outer<<<B_ * 256, 256>>>(Out);
}